// round 16
// baseline (speedup 1.0000x reference)
#include <cuda_runtime.h>
#include <cstdint>

#define BATCH    4096
#define PATH_LEN 512
#define STEPS    511
#define FDIM     64
#define BASE_DIM 256
#define CAP      10240      // per-matrix worklist capacity (mean 8176, +23 sigma)
#define VSTRIDE  20         // sVt row stride in words (80 B: 16B-aligned, conflict-free writes)

typedef unsigned long long ull;

// ---------------- device state (all rewritten every launch) ----------------
__device__ unsigned      g_colmax_bits[PATH_LEN];
__device__ unsigned char g_idx[BATCH * PATH_LEN];
__device__ unsigned      g_cnt[STEPS * BASE_DIM];     // [t][g] member counts
__device__ unsigned      g_startA[BASE_DIM * 512];    // [g][t] exclusive offsets; [g][511] = total
__device__ unsigned      g_list[BASE_DIM * CAP];      // entry = b | (t<<16), t-sorted per g
__device__ unsigned      g_flag[BATCH];               // element progress: next step to apply
__device__ float         g_v[BATCH * FDIM];           // current state vectors

// ---------------- packed f32x2 helpers ----------------
__device__ __forceinline__ ull fma2(ull a, ull b, ull c) {
    ull d; asm("fma.rn.f32x2 %0, %1, %2, %3;" : "=l"(d) : "l"(a), "l"(b), "l"(c)); return d;
}
__device__ __forceinline__ ull add2(ull a, ull b) {
    ull d; asm("add.rn.f32x2 %0, %1, %2;" : "=l"(d) : "l"(a), "l"(b)); return d;
}
__device__ __forceinline__ ull dup2(float x) {
    ull d; asm("mov.b64 %0, {%1, %1};" : "=l"(d) : "f"(x)); return d;
}

// ---------------- prepass kernels ----------------
__global__ void setup_kernel(const float* __restrict__ fiber) {
    int i = blockIdx.x * 256 + threadIdx.x;            // 0..65535
    reinterpret_cast<float4*>(g_v)[i] = reinterpret_cast<const float4*>(fiber)[i];
    if (i < BATCH)    g_flag[i] = 0u;
    if (i < PATH_LEN) g_colmax_bits[i] = __float_as_uint(1.0f);
    int z = i * 2;
    if (z     < STEPS * BASE_DIM) g_cnt[z]     = 0u;
    if (z + 1 < STEPS * BASE_DIM) g_cnt[z + 1] = 0u;
}

__global__ void colmax_kernel(const float* __restrict__ path) {
    int t = threadIdx.x;
    int row0 = blockIdx.x * 16;
    float m = 0.0f;
#pragma unroll
    for (int r = 0; r < 16; r++)
        m = fmaxf(m, path[(size_t)(row0 + r) * PATH_LEN + t]);
    atomicMax(&g_colmax_bits[t], __float_as_uint(m));
}

// idx = clip(trunc(bp*256/mx),0,255); also histogram members per (t, g).
__global__ void idx_count_kernel(const float* __restrict__ path) {
    int b = blockIdx.x, t = threadIdx.x;
    float pv = path[(size_t)b * PATH_LEN + t];
    float mx = __uint_as_float(g_colmax_bits[t]);
    int idx = (int)((pv * 256.0f) / mx);
    idx = min(max(idx, 0), BASE_DIM - 1);
    g_idx[(size_t)b * PATH_LEN + t] = (unsigned char)idx;
    if (t < STEPS) atomicAdd(&g_cnt[t * BASE_DIM + idx], 1u);
}

// Per-matrix exclusive prefix over t (Hillis-Steele over 512, one block per g).
__global__ void scan_kernel() {
    __shared__ unsigned s[512];
    int g = blockIdx.x, t = threadIdx.x;
    unsigned c = (t < STEPS) ? g_cnt[t * BASE_DIM + g] : 0u;
    s[t] = c;
    __syncthreads();
    for (int o = 1; o < 512; o <<= 1) {
        unsigned a = (t >= o) ? s[t - o] : 0u;
        __syncthreads();
        s[t] += a;
        __syncthreads();
    }
    g_startA[g * 512 + t] = s[t] - c;   // exclusive; [511] = grand total
}

// Scatter (b,t) into per-matrix t-sorted worklists.
__global__ void scatter_kernel() {
    __shared__ unsigned cur[BASE_DIM];
    __shared__ unsigned sst[BASE_DIM];
    int t = blockIdx.x, tid = threadIdx.x;
    cur[tid] = 0u;
    sst[tid] = g_startA[tid * 512 + t];
    __syncthreads();
    for (int b = tid; b < BATCH; b += 256) {
        int g = g_idx[(size_t)b * PATH_LEN + t];
        unsigned r = atomicAdd(&cur[g], 1u);
        g_list[g * CAP + sst[g] + r] = (unsigned)b | ((unsigned)t << 16);
    }
}

// ---------------- persistent matrix-stationary transport ----------------
// CTA g owns matrix g in SMEM. Walks its t-sorted worklist in chunks of up to
// 16 ready members (leading-ready rule -> deadlock-free), computes the chunk
// as a register-tiled (k x 64) x (64 x 64) product, and hands states between
// CTAs via g_v (L2) + release/acquire flags.
__global__ __launch_bounds__(256) void transport_kernel(
    const float* __restrict__ conn,
    float* __restrict__ out)
{
    __shared__ float sM[FDIM * FDIM];                    // 16 KB matrix
    __shared__ ull   sRed[4 * 8 * FDIM];                 // 16 KB quarter partials
    __shared__ __align__(16) float sVt[FDIM * VSTRIDE];  // 5 KB member-major v
    __shared__ unsigned sEnt[16];
    __shared__ int sLen;

    const int g   = blockIdx.x;
    const int tid = threadIdx.x;

    {   // load matrix once
        const float4* c4 = reinterpret_cast<const float4*>(conn + (size_t)g * FDIM * FDIM);
        float4* s4 = reinterpret_cast<float4*>(sM);
#pragma unroll
        for (int k = 0; k < 4; k++) s4[k * 256 + tid] = c4[k * 256 + tid];
    }
    const int cnt = (int)g_startA[g * 512 + 511];
    const unsigned* __restrict__ list = g_list + g * CAP;
    int pos = 0;
    __syncthreads();

    const int q = tid >> 6;        // row quarter for compute
    const int j = tid & 63;        // output column

    while (pos < cnt) {
        const int rem = min(16, cnt - pos);

        // ---- warp 0: poll leading-ready run (dup-split, acquire loads) ----
        if (tid < 32) {
            const int lane = tid;
            unsigned e = 0; int b = 0; unsigned tt = 0;
            const bool valid = (lane < rem);
            if (valid) { e = list[pos + lane]; b = (int)(e & 0xffffu); tt = e >> 16; }
            bool dup = false;
#pragma unroll
            for (int s = 0; s < 15; s++) {
                int bs = __shfl_sync(0xffffffffu, b, s);
                if (valid && s < lane && bs == b) dup = true;
            }
            unsigned dupBits = __ballot_sync(0xffffffffu, dup);
            int lim = rem;
            if (dupBits) lim = min(lim, (int)__ffs(dupBits) - 1);   // lim >= 1 always
            int len;
            for (;;) {
                bool ready = false;
                if (lane < lim) {
                    unsigned f;
                    asm volatile("ld.acquire.gpu.global.u32 %0, [%1];"
                                 : "=r"(f) : "l"(g_flag + b) : "memory");
                    ready = (f == tt);
                }
                unsigned rb   = __ballot_sync(0xffffffffu, ready);
                unsigned notr = (~rb) & ((1u << lim) - 1u);
                len = notr ? ((int)__ffs(notr) - 1) : lim;
                if (len > 0) break;
                __nanosleep(150);
            }
            if (lane == 0)  sLen = len;
            if (lane < len) sEnt[lane] = e;
        }
        __syncthreads();
        const int len = sLen;

        // ---- stage member states into SMEM (member-major pairs) ----
        {
            const int m = tid & 15, s4 = tid >> 4;
            float4 v4 = make_float4(0.f, 0.f, 0.f, 0.f);
            if (m < len) {
                int b = (int)(sEnt[m] & 0xffffu);
                v4 = __ldcg(reinterpret_cast<const float4*>(g_v + (size_t)b * FDIM + 4 * s4));
            }
            sVt[(4 * s4 + 0) * VSTRIDE + m] = v4.x;
            sVt[(4 * s4 + 1) * VSTRIDE + m] = v4.y;
            sVt[(4 * s4 + 2) * VSTRIDE + m] = v4.z;
            sVt[(4 * s4 + 3) * VSTRIDE + m] = v4.w;
        }
        __syncthreads();

        // ---- compute: quarter q accumulates rows [16q,16q+16) for all members ----
        ull acc[8];
#pragma unroll
        for (int p = 0; p < 8; p++) acc[p] = 0ull;
        if (len == 16) {
#pragma unroll
            for (int i0 = 0; i0 < 16; i0++) {
                const int i = q * 16 + i0;
                const ull m2 = dup2(sM[i * 64 + j]);
                const ulonglong2* vv = reinterpret_cast<const ulonglong2*>(sVt + i * VSTRIDE);
#pragma unroll
                for (int p2 = 0; p2 < 4; p2++) {
                    ulonglong2 vp = vv[p2];
                    acc[2 * p2]     = fma2(vp.x, m2, acc[2 * p2]);
                    acc[2 * p2 + 1] = fma2(vp.y, m2, acc[2 * p2 + 1]);
                }
            }
        } else {
            const int np2 = (len + 3) >> 2;
            for (int i0 = 0; i0 < 16; i0++) {
                const int i = q * 16 + i0;
                const ull m2 = dup2(sM[i * 64 + j]);
                const ulonglong2* vv = reinterpret_cast<const ulonglong2*>(sVt + i * VSTRIDE);
                for (int p2 = 0; p2 < np2; p2++) {
                    ulonglong2 vp = vv[p2];
                    acc[2 * p2]     = fma2(vp.x, m2, acc[2 * p2]);
                    acc[2 * p2 + 1] = fma2(vp.y, m2, acc[2 * p2 + 1]);
                }
            }
        }
        const int npair = (len + 1) >> 1;
        for (int p = 0; p < npair; p++) sRed[(q * 8 + p) * 64 + j] = acc[p];
        __syncthreads();

        // ---- reduce quarters, store v' (to g_v, or out at final step) ----
#pragma unroll
        for (int r = 0; r < 2; r++) {
            const int o = tid + r * 256;
            const int p = o >> 6, jj = o & 63;
            if (p < npair) {
                ull s = add2(add2(sRed[(0 * 8 + p) * 64 + jj], sRed[(1 * 8 + p) * 64 + jj]),
                             add2(sRed[(2 * 8 + p) * 64 + jj], sRed[(3 * 8 + p) * 64 + jj]));
                unsigned e0 = sEnt[2 * p];
                int b0 = (int)(e0 & 0xffffu); unsigned t0 = e0 >> 16;
                float lo = __uint_as_float((unsigned)s);
                float* d0 = (t0 == STEPS - 1) ? (out + (size_t)b0 * FDIM)
                                              : (g_v + (size_t)b0 * FDIM);
                __stcg(d0 + jj, lo);
                if (2 * p + 1 < len) {
                    unsigned e1 = sEnt[2 * p + 1];
                    int b1 = (int)(e1 & 0xffffu); unsigned t1 = e1 >> 16;
                    float hi = __uint_as_float((unsigned)(s >> 32));
                    float* d1 = (t1 == STEPS - 1) ? (out + (size_t)b1 * FDIM)
                                                  : (g_v + (size_t)b1 * FDIM);
                    __stcg(d1 + jj, hi);
                }
            }
        }
        __syncthreads();   // all v' stores complete before flags release

        if (tid < len) {
            unsigned e = sEnt[tid];
            int b = (int)(e & 0xffffu); unsigned tt = e >> 16;
            if (tt < STEPS - 1) {
                unsigned nv = tt + 1;
                asm volatile("st.release.gpu.global.u32 [%0], %1;"
                             :: "l"(g_flag + b), "r"(nv) : "memory");
            }
        }
        pos += len;
    }
}

extern "C" void kernel_launch(void* const* d_in, const int* in_sizes, int n_in,
                              void* d_out, int out_size)
{
    const float* fiber = (const float*)d_in[0];   // [4096, 64]
    const float* path  = (const float*)d_in[1];   // [4096, 512]
    const float* conn  = (const float*)d_in[2];   // [256, 64, 64]
    float* out         = (float*)d_out;           // [4096, 64]

    (void)in_sizes; (void)n_in; (void)out_size;

    setup_kernel   <<<256, 256>>>(fiber);
    colmax_kernel  <<<BATCH / 16, PATH_LEN>>>(path);
    idx_count_kernel<<<BATCH, PATH_LEN>>>(path);
    scan_kernel    <<<BASE_DIM, 512>>>();
    scatter_kernel <<<STEPS, 256>>>();
    transport_kernel<<<BASE_DIM, 256>>>(conn, out);
}